// round 1
// baseline (speedup 1.0000x reference)
#include <cuda_runtime.h>
#include <cstdint>

// Problem constants
#define PB 8
#define PN 8192
#define PM 2048
#define PC 64
#define PS 32
#define OUTC 67              // 3 + 64
#define R2 1.0f

// Scratch (allocation-free rule: __device__ globals)
__device__ int   g_idx[PB * PM * PS];          // 2 MB
__device__ float g_featT[PB * PN * PC];        // 16 MB, [b][n][c]

// ---------------------------------------------------------------------------
// Kernel 1: ball query — one warp per query, ascending-index scan w/ early exit
// ---------------------------------------------------------------------------
__global__ __launch_bounds__(256) void ball_query_kernel(
    const float* __restrict__ xyz, const float* __restrict__ new_xyz)
{
    const int warpsPerBlock = blockDim.x >> 5;
    const int wid  = blockIdx.x * warpsPerBlock + (threadIdx.x >> 5);
    const int lane = threadIdx.x & 31;
    if (wid >= PB * PM) return;
    const int b = wid / PM;
    const int m = wid - b * PM;

    const float* q = new_xyz + ((size_t)b * PM + m) * 3;
    const float qx = q[0], qy = q[1], qz = q[2];
    // q2 exactly like reference: sum of squares, left-to-right, no fma
    const float q2 = __fadd_rn(__fadd_rn(__fmul_rn(qx, qx), __fmul_rn(qy, qy)),
                               __fmul_rn(qz, qz));

    __shared__ int sidx[8][PS];
    int* slot = sidx[threadIdx.x >> 5];

    const float* base = xyz + (size_t)b * PN * 3;
    int cnt = 0;
    for (int n0 = 0; n0 < PN && cnt < PS; n0 += 32) {
        const int n = n0 + lane;                 // PN % 32 == 0, always in range
        const float px = base[n * 3 + 0];
        const float py = base[n * 3 + 1];
        const float pz = base[n * 3 + 2];
        const float p2 = __fadd_rn(__fadd_rn(__fmul_rn(px, px), __fmul_rn(py, py)),
                                   __fmul_rn(pz, pz));
        const float qp = __fadd_rn(__fadd_rn(__fmul_rn(qx, px), __fmul_rn(qy, py)),
                                   __fmul_rn(qz, pz));
        // dist2 = (q2 + p2) - (2*qp), same association as reference
        const float d2 = __fadd_rn(__fadd_rn(q2, p2), -__fmul_rn(2.0f, qp));
        const bool valid = d2 < R2;
        const unsigned bal = __ballot_sync(0xffffffffu, valid);
        if (valid) {
            const int pos = cnt + __popc(bal & ((1u << lane) - 1u));
            if (pos < PS) slot[pos] = n;
        }
        cnt += __popc(bal);
    }
    __syncwarp();
    const int c = cnt < PS ? cnt : PS;          // always >=1 (self point dist==0)
    const int first = slot[0];
    const int v = (lane < c) ? slot[lane] : first;
    g_idx[(size_t)wid * PS + lane] = v;
}

// ---------------------------------------------------------------------------
// Kernel 2: transpose features (B,C,N) -> featT (B,N,C), 32x32 smem tiles
// ---------------------------------------------------------------------------
__global__ __launch_bounds__(256) void transpose_kernel(const float* __restrict__ f)
{
    __shared__ float tile[32][33];
    const int b  = blockIdx.z;
    const int c0 = blockIdx.y * 32;
    const int n0 = blockIdx.x * 32;
    const int tx = threadIdx.x;   // 0..31
    const int ty = threadIdx.y;   // 0..7

    const float* src = f + ((size_t)b * PC + c0) * PN + n0;
#pragma unroll
    for (int k = 0; k < 32; k += 8)
        tile[ty + k][tx] = src[(size_t)(ty + k) * PN + tx];
    __syncthreads();
#pragma unroll
    for (int k = 0; k < 32; k += 8)
        g_featT[((size_t)b * PN + n0 + ty + k) * PC + c0 + tx] = tile[tx][ty + k];
}

// ---------------------------------------------------------------------------
// Kernel 3: group — one warp per query, lane = sample slot
// reads featT contiguously (float4 x16), stores 128B-coalesced per channel
// ---------------------------------------------------------------------------
__global__ __launch_bounds__(256) void group_kernel(
    const float* __restrict__ xyz, const float* __restrict__ new_xyz,
    float* __restrict__ out)
{
    const int warpsPerBlock = blockDim.x >> 5;
    const int wid  = blockIdx.x * warpsPerBlock + (threadIdx.x >> 5);
    const int lane = threadIdx.x & 31;
    if (wid >= PB * PM) return;
    const int b = wid / PM;
    const int m = wid - b * PM;

    const int n = g_idx[(size_t)wid * PS + lane];

    const float* q = new_xyz + ((size_t)b * PM + m) * 3;
    const float qx = q[0], qy = q[1], qz = q[2];
    const float* p = xyz + ((size_t)b * PN + n) * 3;

    // out[(((b*67 + ch)*M) + m)*S + s]
    const size_t chStride = (size_t)PM * PS;                 // 65536
    size_t basep = (size_t)b * OUTC * chStride + (size_t)m * PS + lane;

    out[basep + 0 * chStride] = p[0] - qx;
    out[basep + 1 * chStride] = p[1] - qy;
    out[basep + 2 * chStride] = p[2] - qz;

    const float4* ft = (const float4*)(g_featT + ((size_t)b * PN + n) * PC);
    float* o = out + basep + 3 * chStride;
#pragma unroll
    for (int c4 = 0; c4 < 16; ++c4) {
        const float4 v = ft[c4];
        o[0 * chStride] = v.x;
        o[1 * chStride] = v.y;
        o[2 * chStride] = v.z;
        o[3 * chStride] = v.w;
        o += 4 * chStride;
    }
}

// ---------------------------------------------------------------------------
extern "C" void kernel_launch(void* const* d_in, const int* in_sizes, int n_in,
                              void* d_out, int out_size)
{
    const float* xyz   = nullptr;
    const float* nxyz  = nullptr;
    const float* feats = nullptr;
    for (int i = 0; i < n_in; ++i) {
        if      (in_sizes[i] == PB * PN * 3) xyz   = (const float*)d_in[i];
        else if (in_sizes[i] == PB * PM * 3) nxyz  = (const float*)d_in[i];
        else if (in_sizes[i] == PB * PC * PN) feats = (const float*)d_in[i];
    }
    float* out = (float*)d_out;
    (void)out_size;

    // ball query: 16384 warps
    ball_query_kernel<<<(PB * PM) / 8, 256>>>(xyz, nxyz);
    // transpose features into L2-resident [B,N,C]
    transpose_kernel<<<dim3(PN / 32, PC / 32, PB), dim3(32, 8)>>>(feats);
    // group + subtract + concat
    group_kernel<<<(PB * PM) / 8, 256>>>(xyz, nxyz, out);
}

// round 2
// speedup vs baseline: 1.7935x; 1.7935x over previous
#include <cuda_runtime.h>
#include <cstdint>

// Problem constants
#define PB 8
#define PN 8192
#define PM 2048
#define PC 64
#define PS 32
#define OUTC 67              // 3 + 64
#define R2 1.0f

// Scratch (allocation-free rule: __device__ globals)
__device__ int    g_idx[PB * PM * PS];          // 2 MB
__device__ float  g_featT[PB * PN * PC];        // 16 MB, [b][n][c]
__device__ float4 g_xyz4[PB * PN];              // 1 MB, (x,y,z,p2)

// ---------------------------------------------------------------------------
// Kernel 0: pack xyz -> float4 with precomputed p2 (reference rounding)
// ---------------------------------------------------------------------------
__global__ __launch_bounds__(256) void pack_kernel(const float* __restrict__ xyz)
{
    const int i = blockIdx.x * blockDim.x + threadIdx.x;   // 0 .. B*N-1
    if (i >= PB * PN) return;
    const float x = xyz[i * 3 + 0];
    const float y = xyz[i * 3 + 1];
    const float z = xyz[i * 3 + 2];
    const float p2 = __fadd_rn(__fadd_rn(__fmul_rn(x, x), __fmul_rn(y, y)),
                               __fmul_rn(z, z));
    g_xyz4[i] = make_float4(x, y, z, p2);
}

// ---------------------------------------------------------------------------
// Kernel 1: ball query — one warp per query, 128 points per iteration
// ---------------------------------------------------------------------------
__global__ __launch_bounds__(256) void ball_query_kernel(
    const float* __restrict__ new_xyz)
{
    const int warpsPerBlock = blockDim.x >> 5;
    const int wid  = blockIdx.x * warpsPerBlock + (threadIdx.x >> 5);
    const int lane = threadIdx.x & 31;
    if (wid >= PB * PM) return;
    const int b = wid / PM;
    const int m = wid - b * PM;

    const float* q = new_xyz + ((size_t)b * PM + m) * 3;
    const float qx = q[0], qy = q[1], qz = q[2];
    const float q2 = __fadd_rn(__fadd_rn(__fmul_rn(qx, qx), __fmul_rn(qy, qy)),
                               __fmul_rn(qz, qz));

    __shared__ int sidx[8][PS];
    int* slot = sidx[threadIdx.x >> 5];

    const float4* base4 = g_xyz4 + (size_t)b * PN;
    int cnt = 0;
    for (int n0 = 0; n0 < PN && cnt < PS; n0 += 128) {
        // issue all 4 chunk loads up front (MLP=4)
        const float4 c0 = base4[n0 +  0 + lane];
        const float4 c1 = base4[n0 + 32 + lane];
        const float4 c2 = base4[n0 + 64 + lane];
        const float4 c3 = base4[n0 + 96 + lane];

        float4 cs[4] = {c0, c1, c2, c3};
#pragma unroll
        for (int k = 0; k < 4; ++k) {
            const float4 p = cs[k];
            const float qp = __fadd_rn(__fadd_rn(__fmul_rn(qx, p.x), __fmul_rn(qy, p.y)),
                                       __fmul_rn(qz, p.z));
            const float d2 = __fadd_rn(__fadd_rn(q2, p.w), -__fmul_rn(2.0f, qp));
            const bool valid = d2 < R2;
            const unsigned bal = __ballot_sync(0xffffffffu, valid);
            if (valid) {
                const int pos = cnt + __popc(bal & ((1u << lane) - 1u));
                if (pos < PS) slot[pos] = n0 + (k << 5) + lane;
            }
            cnt += __popc(bal);
        }
    }
    __syncwarp();
    const int c = cnt < PS ? cnt : PS;          // always >=1 (self point dist==0)
    const int first = slot[0];
    const int v = (lane < c) ? slot[lane] : first;
    g_idx[(size_t)wid * PS + lane] = v;
}

// ---------------------------------------------------------------------------
// Kernel 2: transpose features (B,C,N) -> featT (B,N,C), 32x32 smem tiles
// ---------------------------------------------------------------------------
__global__ __launch_bounds__(256) void transpose_kernel(const float* __restrict__ f)
{
    __shared__ float tile[32][33];
    const int b  = blockIdx.z;
    const int c0 = blockIdx.y * 32;
    const int n0 = blockIdx.x * 32;
    const int tx = threadIdx.x;   // 0..31
    const int ty = threadIdx.y;   // 0..7

    const float* src = f + ((size_t)b * PC + c0) * PN + n0;
#pragma unroll
    for (int k = 0; k < 32; k += 8)
        tile[ty + k][tx] = src[(size_t)(ty + k) * PN + tx];
    __syncthreads();
#pragma unroll
    for (int k = 0; k < 32; k += 8)
        g_featT[((size_t)b * PN + n0 + ty + k) * PC + c0 + tx] = tile[tx][ty + k];
}

// ---------------------------------------------------------------------------
// Kernel 3: group — one warp per query, lane = sample slot
// ---------------------------------------------------------------------------
__global__ __launch_bounds__(256) void group_kernel(
    const float* __restrict__ new_xyz, float* __restrict__ out)
{
    const int warpsPerBlock = blockDim.x >> 5;
    const int wid  = blockIdx.x * warpsPerBlock + (threadIdx.x >> 5);
    const int lane = threadIdx.x & 31;
    if (wid >= PB * PM) return;
    const int b = wid / PM;
    const int m = wid - b * PM;

    const int n = g_idx[(size_t)wid * PS + lane];

    const float* q = new_xyz + ((size_t)b * PM + m) * 3;
    const float qx = q[0], qy = q[1], qz = q[2];
    const float4 p = g_xyz4[(size_t)b * PN + n];

    // out[(((b*67 + ch)*M) + m)*S + s]
    const size_t chStride = (size_t)PM * PS;                 // 65536
    size_t basep = (size_t)b * OUTC * chStride + (size_t)m * PS + lane;

    out[basep + 0 * chStride] = p.x - qx;
    out[basep + 1 * chStride] = p.y - qy;
    out[basep + 2 * chStride] = p.z - qz;

    const float4* ft = (const float4*)(g_featT + ((size_t)b * PN + n) * PC);
    float* o = out + basep + 3 * chStride;
#pragma unroll
    for (int c4 = 0; c4 < 16; ++c4) {
        const float4 v = ft[c4];
        o[0 * chStride] = v.x;
        o[1 * chStride] = v.y;
        o[2 * chStride] = v.z;
        o[3 * chStride] = v.w;
        o += 4 * chStride;
    }
}

// ---------------------------------------------------------------------------
extern "C" void kernel_launch(void* const* d_in, const int* in_sizes, int n_in,
                              void* d_out, int out_size)
{
    const float* xyz   = nullptr;
    const float* nxyz  = nullptr;
    const float* feats = nullptr;
    for (int i = 0; i < n_in; ++i) {
        if      (in_sizes[i] == PB * PN * 3) xyz   = (const float*)d_in[i];
        else if (in_sizes[i] == PB * PM * 3) nxyz  = (const float*)d_in[i];
        else if (in_sizes[i] == PB * PC * PN) feats = (const float*)d_in[i];
    }
    float* out = (float*)d_out;
    (void)out_size;

    pack_kernel<<<(PB * PN + 255) / 256, 256>>>(xyz);
    ball_query_kernel<<<(PB * PM) / 8, 256>>>(nxyz);
    transpose_kernel<<<dim3(PN / 32, PC / 32, PB), dim3(32, 8)>>>(feats);
    group_kernel<<<(PB * PM) / 8, 256>>>(nxyz, out);
}

// round 3
// speedup vs baseline: 2.1510x; 1.1993x over previous
#include <cuda_runtime.h>
#include <cstdint>

// Problem constants
#define PB 8
#define PN 8192
#define PM 2048
#define PC 64
#define PS 32
#define OUTC 67              // 3 + 64
#define R2 1.0f

// Scratch (allocation-free rule: __device__ globals)
__device__ int    g_idx[PB * PM * PS];          // 2 MB
__device__ float  g_featT[PB * PN * PC];        // 16 MB, [b][n][c]
__device__ float4 g_xyz4[PB * PN];              // 1 MB, (x,y,z,p2)

// ---------------------------------------------------------------------------
// Kernel A: fused pack (xyz->float4+p2) + transpose (B,C,N)->(B,N,C)
// blocks 0..4095: transpose tiles; blocks 4096..4351: pack
// ---------------------------------------------------------------------------
__global__ __launch_bounds__(256) void pre_kernel(
    const float* __restrict__ xyz, const float* __restrict__ f)
{
    const int bid = blockIdx.x;
    const int tx = threadIdx.x & 31;
    const int ty = threadIdx.x >> 5;      // 0..7

    if (bid < 4096) {
        __shared__ float tile[32][33];
        const int b    = bid >> 9;        // /512
        const int rem  = bid & 511;
        const int c0   = (rem >> 8) << 5; // 0 or 32
        const int n0   = (rem & 255) << 5;

        const float* src = f + ((size_t)b * PC + c0) * PN + n0;
#pragma unroll
        for (int k = 0; k < 32; k += 8)
            tile[ty + k][tx] = src[(size_t)(ty + k) * PN + tx];
        __syncthreads();
#pragma unroll
        for (int k = 0; k < 32; k += 8)
            g_featT[((size_t)b * PN + n0 + ty + k) * PC + c0 + tx] = tile[tx][ty + k];
    } else {
        const int i = (bid - 4096) * 256 + threadIdx.x;   // 0 .. B*N-1
        const float x = xyz[i * 3 + 0];
        const float y = xyz[i * 3 + 1];
        const float z = xyz[i * 3 + 2];
        const float p2 = __fadd_rn(__fadd_rn(__fmul_rn(x, x), __fmul_rn(y, y)),
                                   __fmul_rn(z, z));
        g_xyz4[i] = make_float4(x, y, z, p2);
    }
}

// ---------------------------------------------------------------------------
// Kernel B: ball query — one warp per query, 128 points per iteration
// ---------------------------------------------------------------------------
__global__ __launch_bounds__(256) void ball_query_kernel(
    const float* __restrict__ new_xyz)
{
    const int warpsPerBlock = blockDim.x >> 5;
    const int wid  = blockIdx.x * warpsPerBlock + (threadIdx.x >> 5);
    const int lane = threadIdx.x & 31;
    if (wid >= PB * PM) return;
    const int b = wid / PM;
    const int m = wid - b * PM;

    const float* q = new_xyz + ((size_t)b * PM + m) * 3;
    const float qx = q[0], qy = q[1], qz = q[2];
    const float q2 = __fadd_rn(__fadd_rn(__fmul_rn(qx, qx), __fmul_rn(qy, qy)),
                               __fmul_rn(qz, qz));

    __shared__ int sidx[8][PS];
    int* slot = sidx[threadIdx.x >> 5];

    const float4* base4 = g_xyz4 + (size_t)b * PN;
    int cnt = 0;
    for (int n0 = 0; n0 < PN && cnt < PS; n0 += 128) {
        const float4 c0 = base4[n0 +  0 + lane];
        const float4 c1 = base4[n0 + 32 + lane];
        const float4 c2 = base4[n0 + 64 + lane];
        const float4 c3 = base4[n0 + 96 + lane];

        float4 cs[4] = {c0, c1, c2, c3};
#pragma unroll
        for (int k = 0; k < 4; ++k) {
            const float4 p = cs[k];
            const float qp = __fadd_rn(__fadd_rn(__fmul_rn(qx, p.x), __fmul_rn(qy, p.y)),
                                       __fmul_rn(qz, p.z));
            const float d2 = __fadd_rn(__fadd_rn(q2, p.w), -__fmul_rn(2.0f, qp));
            const bool valid = d2 < R2;
            const unsigned bal = __ballot_sync(0xffffffffu, valid);
            if (valid) {
                const int pos = cnt + __popc(bal & ((1u << lane) - 1u));
                if (pos < PS) slot[pos] = n0 + (k << 5) + lane;
            }
            cnt += __popc(bal);
        }
    }
    __syncwarp();
    const int c = cnt < PS ? cnt : PS;          // always >=1 (self point dist==0)
    const int first = slot[0];
    const int v = (lane < c) ? slot[lane] : first;
    g_idx[(size_t)wid * PS + lane] = v;
}

// ---------------------------------------------------------------------------
// Kernel C: group v2 — warp per query, smem-staged coalesced gather
//   Phase 1: for each sample j (n via shfl), lanes read featT[n][lane] and
//            featT[n][32+lane] (coalesced) -> smem row (stride 65, no bank
//            conflicts in either phase)
//   Phase 2: lane = s, loop channels; coalesced 128B stores
// ---------------------------------------------------------------------------
__global__ __launch_bounds__(128) void group_kernel(
    const float* __restrict__ new_xyz, float* __restrict__ out)
{
    __shared__ float sf[128 * 65];               // 33,280 B
    const int w    = threadIdx.x >> 5;           // warp in block, 0..3
    const int lane = threadIdx.x & 31;
    const int q    = blockIdx.x * 4 + w;         // global query, 0..16383
    const int b    = q >> 11;
    const int m    = q & (PM - 1);

    // lane j holds neighbor index of sample j
    const int n_reg = g_idx[(size_t)q * PS + lane];

    const float* fb = g_featT + (size_t)b * PN * PC;
    float* srowbase = sf + (size_t)(w * 32) * 65;

#pragma unroll 8
    for (int j = 0; j < 32; ++j) {
        const int n = __shfl_sync(0xffffffffu, n_reg, j);
        const float* src = fb + (size_t)n * PC;
        const float a0 = src[lane];
        const float a1 = src[32 + lane];
        float* dst = srowbase + j * 65;
        dst[lane]      = a0;
        dst[32 + lane] = a1;
    }
    __syncwarp();

    // Phase 2: lane = sample slot s
    const float* qp = new_xyz + (size_t)q * 3;
    const float qx = qp[0], qy = qp[1], qz = qp[2];
    const float4 p = g_xyz4[(size_t)b * PN + n_reg];

    const size_t chStride = (size_t)PM * PS;     // 65536
    const size_t basep = (size_t)b * OUTC * chStride + (size_t)m * PS + lane;

    out[basep + 0 * chStride] = p.x - qx;
    out[basep + 1 * chStride] = p.y - qy;
    out[basep + 2 * chStride] = p.z - qz;

    const float* srow = srowbase + lane * 65;
    float* o = out + basep + 3 * chStride;
#pragma unroll
    for (int c = 0; c < PC; ++c)
        o[(size_t)c * chStride] = srow[c];
}

// ---------------------------------------------------------------------------
extern "C" void kernel_launch(void* const* d_in, const int* in_sizes, int n_in,
                              void* d_out, int out_size)
{
    const float* xyz   = nullptr;
    const float* nxyz  = nullptr;
    const float* feats = nullptr;
    for (int i = 0; i < n_in; ++i) {
        if      (in_sizes[i] == PB * PN * 3) xyz   = (const float*)d_in[i];
        else if (in_sizes[i] == PB * PM * 3) nxyz  = (const float*)d_in[i];
        else if (in_sizes[i] == PB * PC * PN) feats = (const float*)d_in[i];
    }
    float* out = (float*)d_out;
    (void)out_size;

    pre_kernel<<<4096 + 256, 256>>>(xyz, feats);          // pack + transpose
    ball_query_kernel<<<(PB * PM) / 8, 256>>>(nxyz);      // 16384 warps
    group_kernel<<<(PB * PM) / 4, 128>>>(nxyz, out);      // warp per query
}